// round 1
// baseline (speedup 1.0000x reference)
#include <cuda_runtime.h>
#include <cuda_bf16.h>
#include <mma.h>

using namespace nvcuda;

#define B_ROWS 4096
#define S_ROWS 2048
#define DDIM   2496

// bf16 scratch + fp32 row norms (device globals: allocation-free rule)
__device__ __align__(16) __nv_bfloat16 g_Xb[(size_t)B_ROWS * DDIM];
__device__ __align__(16) __nv_bfloat16 g_Mb[(size_t)S_ROWS * DDIM];
__device__ float g_xsq[B_ROWS];
__device__ float g_msq[S_ROWS];

// ---------------------------------------------------------------------------
// Convert fp32 rows -> bf16, and compute fp32 row squared-norms.
// which==0: observation -> g_Xb/g_xsq ; which==1: observation_matrix -> g_Mb/g_msq
// ---------------------------------------------------------------------------
__global__ void convert_kernel(const float* __restrict__ src, int which) {
    __nv_bfloat16* dst = which ? g_Mb : g_Xb;
    float*         sqv = which ? g_msq : g_xsq;

    const int row = blockIdx.x;
    const float4* s4 = reinterpret_cast<const float4*>(src + (size_t)row * DDIM);
    uint2*        d2 = reinterpret_cast<uint2*>(dst + (size_t)row * DDIM);

    float acc = 0.f;
    const int n4 = DDIM / 4;  // 624
    for (int i = threadIdx.x; i < n4; i += blockDim.x) {
        float4 f = s4[i];
        acc = fmaf(f.x, f.x, acc);
        acc = fmaf(f.y, f.y, acc);
        acc = fmaf(f.z, f.z, acc);
        acc = fmaf(f.w, f.w, acc);
        __nv_bfloat162 lo = __floats2bfloat162_rn(f.x, f.y);
        __nv_bfloat162 hi = __floats2bfloat162_rn(f.z, f.w);
        uint2 u;
        u.x = *reinterpret_cast<unsigned int*>(&lo);
        u.y = *reinterpret_cast<unsigned int*>(&hi);
        d2[i] = u;
    }

    // block reduce
    #pragma unroll
    for (int o = 16; o > 0; o >>= 1)
        acc += __shfl_down_sync(0xFFFFFFFFu, acc, o);

    __shared__ float red[8];
    const int lane = threadIdx.x & 31;
    const int wid  = threadIdx.x >> 5;
    if (lane == 0) red[wid] = acc;
    __syncthreads();
    if (threadIdx.x == 0) {
        float t = 0.f;
        const int nw = blockDim.x >> 5;
        for (int i = 0; i < nw; i++) t += red[i];
        sqv[row] = t;
    }
}

// ---------------------------------------------------------------------------
// bf16 wmma GEMM with fused squared-distance epilogue.
// C[b][s] = (xsq[b] + msq[s] - 2 * sum_d X[b,d]*M[s,d]) * (-1/500)
// CTA tile 128x128, BK=32, 8 warps (2x4), warp tile 64x32.
// ---------------------------------------------------------------------------
#define BM 128
#define BN 128
#define BK 32
#define LDT 40                 // padded SMEM leading dim (multiple of 8 elems)
#define NT  (DDIM / BK)        // 78
#define U4_PER_ROW (DDIM / 8)  // 312 uint4 per global row

__global__ __launch_bounds__(256, 1)
void gemm_sqdist_kernel(float* __restrict__ out) {
    __shared__ __align__(16) __nv_bfloat16 As[2][BM * LDT];
    __shared__ __align__(16) __nv_bfloat16 Bs[2][BN * LDT];

    const int tid  = threadIdx.x;
    const int lane = tid & 31;
    const int warp = tid >> 5;
    const int warp_m = warp >> 2;  // 0..1
    const int warp_n = warp & 3;   // 0..3

    const int bm = blockIdx.y * BM;
    const int bn = blockIdx.x * BN;

    const uint4* gA = reinterpret_cast<const uint4*>(g_Xb);
    const uint4* gB = reinterpret_cast<const uint4*>(g_Mb);

    wmma::fragment<wmma::accumulator, 16, 16, 16, float> c[4][2];
    #pragma unroll
    for (int i = 0; i < 4; i++)
        #pragma unroll
        for (int j = 0; j < 2; j++)
            wmma::fill_fragment(c[i][j], 0.0f);

    // Tile load mapping: 512 uint4 per tile (128 rows x 4 chunks of 16B).
    // Thread q-th item: idx = tid + q*256; row = idx>>2, chunk = idx&3.
    uint4 ra[2], rb[2];

    // prologue: load kt=0
    #pragma unroll
    for (int q = 0; q < 2; q++) {
        const int idx = tid + q * 256;
        const int row = idx >> 2, ch = idx & 3;
        ra[q] = gA[(size_t)(bm + row) * U4_PER_ROW + ch];
        rb[q] = gB[(size_t)(bn + row) * U4_PER_ROW + ch];
    }
    #pragma unroll
    for (int q = 0; q < 2; q++) {
        const int idx = tid + q * 256;
        const int row = idx >> 2, ch = idx & 3;
        *reinterpret_cast<uint4*>(&As[0][row * LDT + ch * 8]) = ra[q];
        *reinterpret_cast<uint4*>(&Bs[0][row * LDT + ch * 8]) = rb[q];
    }
    __syncthreads();

    for (int kt = 0; kt < NT; kt++) {
        const int cur = kt & 1;
        const int nxt = cur ^ 1;
        const bool pf = (kt + 1 < NT);

        // prefetch next tile into registers (overlaps with compute below)
        if (pf) {
            #pragma unroll
            for (int q = 0; q < 2; q++) {
                const int idx = tid + q * 256;
                const int row = idx >> 2, ch = idx & 3;
                ra[q] = gA[(size_t)(bm + row) * U4_PER_ROW + (kt + 1) * 4 + ch];
                rb[q] = gB[(size_t)(bn + row) * U4_PER_ROW + (kt + 1) * 4 + ch];
            }
        }

        // compute on current buffer
        #pragma unroll
        for (int kk = 0; kk < BK; kk += 16) {
            wmma::fragment<wmma::matrix_a, 16, 16, 16, __nv_bfloat16, wmma::row_major> a[4];
            wmma::fragment<wmma::matrix_b, 16, 16, 16, __nv_bfloat16, wmma::col_major> b[2];
            #pragma unroll
            for (int i = 0; i < 4; i++)
                wmma::load_matrix_sync(a[i], &As[cur][(warp_m * 64 + i * 16) * LDT + kk], LDT);
            #pragma unroll
            for (int j = 0; j < 2; j++)
                wmma::load_matrix_sync(b[j], &Bs[cur][(warp_n * 32 + j * 16) * LDT + kk], LDT);
            #pragma unroll
            for (int i = 0; i < 4; i++)
                #pragma unroll
                for (int j = 0; j < 2; j++)
                    wmma::mma_sync(c[i][j], a[i], b[j], c[i][j]);
        }

        if (pf) {
            #pragma unroll
            for (int q = 0; q < 2; q++) {
                const int idx = tid + q * 256;
                const int row = idx >> 2, ch = idx & 3;
                *reinterpret_cast<uint4*>(&As[nxt][row * LDT + ch * 8]) = ra[q];
                *reinterpret_cast<uint4*>(&Bs[nxt][row * LDT + ch * 8]) = rb[q];
            }
        }
        __syncthreads();
    }

    // Epilogue: stage accumulators through SMEM (reuse As), fuse norms + scale.
    float* stage = reinterpret_cast<float*>(&As[0][0]) + warp * 256;  // 1KB/warp
    const float scale = -2.0e-3f;  // 1 / (-500)

    #pragma unroll
    for (int i = 0; i < 4; i++) {
        #pragma unroll
        for (int j = 0; j < 2; j++) {
            wmma::store_matrix_sync(stage, c[i][j], 16, wmma::mem_row_major);
            __syncwarp();
            const int gr0 = bm + warp_m * 64 + i * 16;
            const int gc0 = bn + warp_n * 32 + j * 16;
            #pragma unroll
            for (int e = lane; e < 256; e += 32) {
                const int r = e >> 4, cl = e & 15;
                const float cr = stage[e];
                out[(size_t)(gr0 + r) * S_ROWS + gc0 + cl] =
                    (g_xsq[gr0 + r] + g_msq[gc0 + cl] - 2.0f * cr) * scale;
            }
            __syncwarp();
        }
    }
}

// ---------------------------------------------------------------------------
extern "C" void kernel_launch(void* const* d_in, const int* in_sizes, int n_in,
                              void* d_out, int out_size) {
    const float* observation        = (const float*)d_in[0];  // [4096, 16,13,12]
    const float* observation_matrix = (const float*)d_in[1];  // [2048, 16,13,12]
    float* out = (float*)d_out;                                // [4096, 2048]

    convert_kernel<<<B_ROWS, 256>>>(observation, 0);
    convert_kernel<<<S_ROWS, 256>>>(observation_matrix, 1);

    dim3 grid(S_ROWS / BN, B_ROWS / BM);  // (16, 32)
    gemm_sqdist_kernel<<<grid, 256>>>(out);
}

// round 3
// speedup vs baseline: 1.8981x; 1.8981x over previous
#include <cuda_runtime.h>
#include <cuda_bf16.h>
#include <cstdint>

#define B_ROWS 4096
#define S_ROWS 2048
#define DDIM   2496

// ---------------- device scratch (allocation-free rule) ----------------
__device__ __align__(16) __nv_bfloat16 g_Xb[(size_t)B_ROWS * DDIM];
__device__ __align__(16) __nv_bfloat16 g_Mb[(size_t)S_ROWS * DDIM];
__device__ float g_xsq[B_ROWS];
__device__ float g_msq[S_ROWS];

// ---------------- helpers ----------------
__device__ __forceinline__ uint32_t smem_to_u32(const void* p) {
    uint32_t a;
    asm("{ .reg .u64 t; cvta.to.shared.u64 t, %1; cvt.u32.u64 %0, t; }" : "=r"(a) : "l"(p));
    return a;
}
#define SWZ_C(row, c) ((c) ^ (((row) & 7) << 4))   // SW128: col-bytes xor, rows of 128B

#define CP_ASYNC16(dst, src) \
    asm volatile("cp.async.cg.shared.global [%0], [%1], 16;" :: "r"(dst), "l"(src))
#define CP_COMMIT() asm volatile("cp.async.commit_group;" ::: "memory")
#define CP_WAIT1()  asm volatile("cp.async.wait_group 1;" ::: "memory")

#define LDSM_X4(r, addr) \
    asm volatile("ldmatrix.sync.aligned.m8n8.x4.shared.b16 {%0,%1,%2,%3}, [%4];" \
        : "=r"((r)[0]), "=r"((r)[1]), "=r"((r)[2]), "=r"((r)[3]) : "r"(addr))

#define MMA16816(d, a, b0, b1) \
    asm volatile("mma.sync.aligned.m16n8k16.row.col.f32.bf16.bf16.f32 " \
        "{%0,%1,%2,%3}, {%4,%5,%6,%7}, {%8,%9}, {%0,%1,%2,%3};" \
        : "+f"((d)[0]), "+f"((d)[1]), "+f"((d)[2]), "+f"((d)[3]) \
        : "r"((a)[0]), "r"((a)[1]), "r"((a)[2]), "r"((a)[3]), "r"(b0), "r"(b1))

// ---------------------------------------------------------------------------
// Convert fp32 rows -> bf16 and fp32 row squared-norms.
// ---------------------------------------------------------------------------
__global__ void convert_kernel(const float* __restrict__ src, int which) {
    __nv_bfloat16* dst = which ? g_Mb : g_Xb;
    float*         sqv = which ? g_msq : g_xsq;

    const int row = blockIdx.x;
    const float4* s4 = reinterpret_cast<const float4*>(src + (size_t)row * DDIM);
    uint2*        d2 = reinterpret_cast<uint2*>(dst + (size_t)row * DDIM);

    float acc = 0.f;
    const int n4 = DDIM / 4;  // 624
    for (int i = threadIdx.x; i < n4; i += blockDim.x) {
        float4 f = s4[i];
        acc = fmaf(f.x, f.x, acc);
        acc = fmaf(f.y, f.y, acc);
        acc = fmaf(f.z, f.z, acc);
        acc = fmaf(f.w, f.w, acc);
        __nv_bfloat162 lo = __floats2bfloat162_rn(f.x, f.y);
        __nv_bfloat162 hi = __floats2bfloat162_rn(f.z, f.w);
        uint2 u;
        u.x = *reinterpret_cast<unsigned int*>(&lo);
        u.y = *reinterpret_cast<unsigned int*>(&hi);
        d2[i] = u;
    }
    #pragma unroll
    for (int o = 16; o > 0; o >>= 1) acc += __shfl_down_sync(0xFFFFFFFFu, acc, o);

    __shared__ float red[8];
    const int lane = threadIdx.x & 31;
    const int wid  = threadIdx.x >> 5;
    if (lane == 0) red[wid] = acc;
    __syncthreads();
    if (threadIdx.x == 0) {
        float t = 0.f;
        const int nw = blockDim.x >> 5;
        for (int i = 0; i < nw; i++) t += red[i];
        sqv[row] = t;
    }
}

// ---------------------------------------------------------------------------
// mma.sync bf16 GEMM, CTA tile 256x128, BK=64, 8 warps (4x2), warp tile 64x64.
// SW128-swizzled SMEM + ldmatrix, cp.async 3-stage pipeline.
// Fused epilogue: out = (xsq + msq - 2*dot) * (-1/500)
// ---------------------------------------------------------------------------
#define BM 256
#define BN 128
#define BK 64
#define NSTAGE 3
#define NT (DDIM / BK)                  // 39
#define A_BYTES (BM * 128)              // 32768
#define B_BYTES (BN * 128)              // 16384
#define STAGE_BYTES (A_BYTES + B_BYTES) // 49152
#define U4_PER_ROW (DDIM / 8)           // 312

__global__ __launch_bounds__(256, 1)
void gemm_sqdist_mma(float* __restrict__ out) {
    extern __shared__ char dyn_smem[];
    __shared__ float s_xsq[BM];
    __shared__ float s_msq[BN];

    const int tid  = threadIdx.x;
    const int lane = tid & 31;
    const int warp = tid >> 5;
    const int wm   = warp & 3;   // 0..3  -> M rows [wm*64, wm*64+64)
    const int wn   = warp >> 2;  // 0..1  -> N cols [wn*64, wn*64+64)

    const int bm = blockIdx.y * BM;
    const int bn = blockIdx.x * BN;

    const uint32_t dbase = (smem_to_u32(dyn_smem) + 1023u) & ~1023u;
    uint32_t sA[NSTAGE], sB[NSTAGE];
    #pragma unroll
    for (int s = 0; s < NSTAGE; s++) {
        sA[s] = dbase + s * STAGE_BYTES;
        sB[s] = sA[s] + A_BYTES;
    }

    s_xsq[tid] = g_xsq[bm + tid];
    if (tid < BN) s_msq[tid] = g_msq[bn + tid];

    const __nv_bfloat16* gA = g_Xb + (size_t)bm * DDIM;
    const __nv_bfloat16* gB = g_Mb + (size_t)bn * DDIM;

    // ---- stage loader via cp.async: A 2048 chunks(16B), B 1024 chunks ----
    auto load_stage = [&](int kt, int buf) {
        const int kb = kt * 8;  // uint4 index at row start
        #pragma unroll
        for (int q = 0; q < 8; q++) {
            const int item = q * 256 + tid;
            const int row = item >> 3, i = item & 7;
            const uint32_t dst = sA[buf] + row * 128 + SWZ_C(row, i * 16);
            CP_ASYNC16(dst, gA + (size_t)row * DDIM + (size_t)(kb + i) * 8);
        }
        #pragma unroll
        for (int q = 0; q < 4; q++) {
            const int item = q * 256 + tid;
            const int row = item >> 3, i = item & 7;
            const uint32_t dst = sB[buf] + row * 128 + SWZ_C(row, i * 16);
            CP_ASYNC16(dst, gB + (size_t)row * DDIM + (size_t)(kb + i) * 8);
        }
    };

    // ---- per-lane ldmatrix base addressing ----
    // A: lanes 0-7 rows 0-7 @k0 | 8-15 rows 8-15 @k0 | 16-23 rows 0-7 @k8 | 24-31 rows 8-15 @k8
    const int a_row  = (lane & 7) + ((lane >> 3) & 1) * 8;
    const int a_koff = ((lane >> 4) & 1) * 16;              // bytes
    const uint32_t a_base_off = (uint32_t)(wm * 64 + a_row) * 128;
    const int a_xm = (a_row & 7) << 4;
    // B: lanes 0-7 rows n0-7 @k0 | 8-15 n0-7 @k8 | 16-23 n8-15 @k0 | 24-31 n8-15 @k8
    const int b_row  = (lane & 7) + ((lane >> 4) & 1) * 8;
    const int b_koff = ((lane >> 3) & 1) * 16;
    const uint32_t b_base_off = (uint32_t)(wn * 64 + b_row) * 128;
    const int b_xm = (b_row & 7) << 4;

    float c[4][8][4];
    #pragma unroll
    for (int mi = 0; mi < 4; mi++)
        #pragma unroll
        for (int ni = 0; ni < 8; ni++)
            #pragma unroll
            for (int e = 0; e < 4; e++) c[mi][ni][e] = 0.f;

    // ---- pipeline prologue ----
    load_stage(0, 0); CP_COMMIT();
    load_stage(1, 1); CP_COMMIT();
    CP_WAIT1();
    __syncthreads();

    for (int kt = 0; kt < NT; kt++) {
        const int buf = kt % NSTAGE;

        // prefetch kt+2
        if (kt + 2 < NT) load_stage(kt + 2, (kt + 2) % NSTAGE);
        CP_COMMIT();

        const uint32_t aw = sA[buf] + a_base_off;
        const uint32_t bw = sB[buf] + b_base_off;

        #pragma unroll
        for (int q = 0; q < 4; q++) {   // k16 steps within BK=64
            const uint32_t aq = (uint32_t)((q * 32 + a_koff) ^ a_xm);
            const uint32_t bq = (uint32_t)((q * 32 + b_koff) ^ b_xm);
            uint32_t a[4][4];
            #pragma unroll
            for (int mi = 0; mi < 4; mi++) LDSM_X4(a[mi], aw + mi * 2048 + aq);
            uint32_t b[4][4];
            #pragma unroll
            for (int nj = 0; nj < 4; nj++) LDSM_X4(b[nj], bw + nj * 2048 + bq);
            #pragma unroll
            for (int mi = 0; mi < 4; mi++)
                #pragma unroll
                for (int ni = 0; ni < 8; ni++)
                    MMA16816(c[mi][ni], a[mi], b[ni >> 1][(ni & 1) * 2], b[ni >> 1][(ni & 1) * 2 + 1]);
        }

        CP_WAIT1();
        __syncthreads();
    }

    // ---- fused epilogue ----
    const int gid = lane >> 2, tig = lane & 3;
    const float scale = -2.0e-3f;  // 1/(-500)

    #pragma unroll
    for (int mi = 0; mi < 4; mi++) {
        const int r0 = wm * 64 + mi * 16 + gid;     // local row
        const float xs0 = s_xsq[r0];
        const float xs1 = s_xsq[r0 + 8];
        float* o0 = out + (size_t)(bm + r0) * S_ROWS + bn;
        float* o1 = o0 + (size_t)8 * S_ROWS;
        #pragma unroll
        for (int ni = 0; ni < 8; ni++) {
            const int col = wn * 64 + ni * 8 + tig * 2;  // local col
            const float ms0 = s_msq[col];
            const float ms1 = s_msq[col + 1];
            float2 v0, v1;
            v0.x = (xs0 + ms0 - 2.f * c[mi][ni][0]) * scale;
            v0.y = (xs0 + ms1 - 2.f * c[mi][ni][1]) * scale;
            v1.x = (xs1 + ms0 - 2.f * c[mi][ni][2]) * scale;
            v1.y = (xs1 + ms1 - 2.f * c[mi][ni][3]) * scale;
            *reinterpret_cast<float2*>(o0 + col) = v0;
            *reinterpret_cast<float2*>(o1 + col) = v1;
        }
    }
}

// ---------------------------------------------------------------------------
extern "C" void kernel_launch(void* const* d_in, const int* in_sizes, int n_in,
                              void* d_out, int out_size) {
    const float* observation        = (const float*)d_in[0];  // [4096, 2496]
    const float* observation_matrix = (const float*)d_in[1];  // [2048, 2496]
    float* out = (float*)d_out;                                // [4096, 2048]

    convert_kernel<<<B_ROWS, 256>>>(observation, 0);
    convert_kernel<<<S_ROWS, 256>>>(observation_matrix, 1);

    const int dyn_bytes = NSTAGE * STAGE_BYTES + 1024;  // 148480
    cudaFuncSetAttribute(gemm_sqdist_mma, cudaFuncAttributeMaxDynamicSharedMemorySize, dyn_bytes);
    dim3 grid(S_ROWS / BN, B_ROWS / BM);  // (16, 16) = 256 CTAs
    gemm_sqdist_mma<<<grid, 256, dyn_bytes>>>(out);
}

// round 4
// speedup vs baseline: 2.2990x; 1.2112x over previous
#include <cuda_runtime.h>
#include <cuda_bf16.h>
#include <cstdint>

#define B_ROWS 4096
#define S_ROWS 2048
#define DDIM   2496

// ---------------- device scratch (allocation-free rule) ----------------
__device__ __align__(16) __nv_bfloat16 g_Xb[(size_t)B_ROWS * DDIM];
__device__ __align__(16) __nv_bfloat16 g_Mb[(size_t)S_ROWS * DDIM];
__device__ float g_xsq[B_ROWS];
__device__ float g_msq[S_ROWS];

// ---------------- helpers ----------------
__device__ __forceinline__ uint32_t smem_to_u32(const void* p) {
    uint32_t a;
    asm("{ .reg .u64 t; cvta.to.shared.u64 t, %1; cvt.u32.u64 %0, t; }" : "=r"(a) : "l"(p));
    return a;
}
#define SWZ_C(row, c) ((c) ^ (((row) & 7) << 4))   // SW128 swizzle within 128B rows

#define CP_ASYNC16(dst, src) \
    asm volatile("cp.async.cg.shared.global [%0], [%1], 16;" :: "r"(dst), "l"(src))
#define CP_COMMIT() asm volatile("cp.async.commit_group;" ::: "memory")
#define CP_WAIT1()  asm volatile("cp.async.wait_group 1;" ::: "memory")

#define LDSM_X4(r, addr) \
    asm volatile("ldmatrix.sync.aligned.m8n8.x4.shared.b16 {%0,%1,%2,%3}, [%4];" \
        : "=r"((r)[0]), "=r"((r)[1]), "=r"((r)[2]), "=r"((r)[3]) : "r"(addr))

#define MMA16816(d, a, b0, b1) \
    asm volatile("mma.sync.aligned.m16n8k16.row.col.f32.bf16.bf16.f32 " \
        "{%0,%1,%2,%3}, {%4,%5,%6,%7}, {%8,%9}, {%0,%1,%2,%3};" \
        : "+f"((d)[0]), "+f"((d)[1]), "+f"((d)[2]), "+f"((d)[3]) \
        : "r"((a)[0]), "r"((a)[1]), "r"((a)[2]), "r"((a)[3]), "r"(b0), "r"(b1))

// ---------------------------------------------------------------------------
// Fused convert: warp-per-row, both tensors in one launch.
// Rows [0,4096) -> X, rows [4096,6144) -> M. fp32 -> bf16 + fp32 sq-norm.
// ---------------------------------------------------------------------------
#define CONV_WPB 8   // warps per block
__global__ __launch_bounds__(256, 4)
void convert_fused(const float* __restrict__ X, const float* __restrict__ M) {
    const int lane  = threadIdx.x & 31;
    const int gwarp = blockIdx.x * CONV_WPB + (threadIdx.x >> 5);

    const float* src;
    __nv_bfloat16* dst;
    float* sqv;
    int row;
    if (gwarp < B_ROWS) {
        row = gwarp;             src = X + (size_t)row * DDIM;
        dst = g_Xb + (size_t)row * DDIM;  sqv = &g_xsq[row];
    } else {
        row = gwarp - B_ROWS;    src = M + (size_t)row * DDIM;
        dst = g_Mb + (size_t)row * DDIM;  sqv = &g_msq[row];
    }

    const float4* s4 = reinterpret_cast<const float4*>(src);
    uint2*        d2 = reinterpret_cast<uint2*>(dst);

    float acc = 0.f;
    const int n4 = DDIM / 4;  // 624 = 19.5 per lane
    #pragma unroll 4
    for (int i = lane; i < n4; i += 32) {
        float4 f = s4[i];
        acc = fmaf(f.x, f.x, acc);
        acc = fmaf(f.y, f.y, acc);
        acc = fmaf(f.z, f.z, acc);
        acc = fmaf(f.w, f.w, acc);
        __nv_bfloat162 lo = __floats2bfloat162_rn(f.x, f.y);
        __nv_bfloat162 hi = __floats2bfloat162_rn(f.z, f.w);
        uint2 u;
        u.x = *reinterpret_cast<unsigned int*>(&lo);
        u.y = *reinterpret_cast<unsigned int*>(&hi);
        d2[i] = u;
    }
    #pragma unroll
    for (int o = 16; o > 0; o >>= 1) acc += __shfl_down_sync(0xFFFFFFFFu, acc, o);
    if (lane == 0) *sqv = acc;
}

// ---------------------------------------------------------------------------
// mma.sync bf16 GEMM, CTA tile 128x128, BK=64, 4 warps (2x2), warp tile 64x64.
// SW128 swizzle + ldmatrix, cp.async 3-stage pipeline, 2 CTAs/SM.
// Fused epilogue: out = (xsq + msq - 2*dot) * (-1/500)
// ---------------------------------------------------------------------------
#define BM 128
#define BN 128
#define BK 64
#define NSTAGE 3
#define NT (DDIM / BK)                  // 39
#define A_BYTES (BM * 128)              // 16384
#define B_BYTES (BN * 128)              // 16384
#define STAGE_BYTES (A_BYTES + B_BYTES) // 32768

__global__ __launch_bounds__(128, 2)
void gemm_sqdist_mma(float* __restrict__ out) {
    extern __shared__ char dyn_smem[];
    __shared__ float s_xsq[BM];
    __shared__ float s_msq[BN];

    const int tid  = threadIdx.x;
    const int lane = tid & 31;
    const int warp = tid >> 5;
    const int wm   = warp & 1;   // 0..1 -> M rows [wm*64, wm*64+64)
    const int wn   = warp >> 1;  // 0..1 -> N cols [wn*64, wn*64+64)

    const int bm = blockIdx.y * BM;
    const int bn = blockIdx.x * BN;

    const uint32_t dbase = (smem_to_u32(dyn_smem) + 1023u) & ~1023u;
    uint32_t sA[NSTAGE], sB[NSTAGE];
    #pragma unroll
    for (int s = 0; s < NSTAGE; s++) {
        sA[s] = dbase + s * STAGE_BYTES;
        sB[s] = sA[s] + A_BYTES;
    }

    s_xsq[tid] = g_xsq[bm + tid];
    s_msq[tid] = g_msq[bn + tid];

    const __nv_bfloat16* gA = g_Xb + (size_t)bm * DDIM;
    const __nv_bfloat16* gB = g_Mb + (size_t)bn * DDIM;

    // ---- stage loader via cp.async: A 1024 chunks(16B) + B 1024, 128 thr ----
    auto load_stage = [&](int kt, int buf) {
        const int kb = kt * 8;  // uint4 index at row start
        #pragma unroll
        for (int q = 0; q < 8; q++) {
            const int item = q * 128 + tid;
            const int row = item >> 3, i = item & 7;
            const uint32_t dst = sA[buf] + row * 128 + SWZ_C(row, i * 16);
            CP_ASYNC16(dst, gA + (size_t)row * DDIM + (size_t)(kb + i) * 8);
        }
        #pragma unroll
        for (int q = 0; q < 8; q++) {
            const int item = q * 128 + tid;
            const int row = item >> 3, i = item & 7;
            const uint32_t dst = sB[buf] + row * 128 + SWZ_C(row, i * 16);
            CP_ASYNC16(dst, gB + (size_t)row * DDIM + (size_t)(kb + i) * 8);
        }
    };

    // ---- per-lane ldmatrix addressing ----
    const int a_row  = (lane & 7) + ((lane >> 3) & 1) * 8;
    const int a_koff = ((lane >> 4) & 1) * 16;
    const uint32_t a_base_off = (uint32_t)(wm * 64 + a_row) * 128;
    const int a_xm = (a_row & 7) << 4;
    const int b_row  = (lane & 7) + ((lane >> 4) & 1) * 8;
    const int b_koff = ((lane >> 3) & 1) * 16;
    const uint32_t b_base_off = (uint32_t)(wn * 64 + b_row) * 128;
    const int b_xm = (b_row & 7) << 4;

    float c[4][8][4];
    #pragma unroll
    for (int mi = 0; mi < 4; mi++)
        #pragma unroll
        for (int ni = 0; ni < 8; ni++)
            #pragma unroll
            for (int e = 0; e < 4; e++) c[mi][ni][e] = 0.f;

    // ---- pipeline prologue ----
    load_stage(0, 0); CP_COMMIT();
    load_stage(1, 1); CP_COMMIT();
    CP_WAIT1();
    __syncthreads();

    for (int kt = 0; kt < NT; kt++) {
        const int buf = kt % NSTAGE;

        if (kt + 2 < NT) load_stage(kt + 2, (kt + 2) % NSTAGE);
        CP_COMMIT();

        const uint32_t aw = sA[buf] + a_base_off;
        const uint32_t bw = sB[buf] + b_base_off;

        #pragma unroll
        for (int q = 0; q < 4; q++) {   // k16 steps within BK=64
            const uint32_t aq = (uint32_t)((q * 32 + a_koff) ^ a_xm);
            const uint32_t bq = (uint32_t)((q * 32 + b_koff) ^ b_xm);
            uint32_t a[4][4];
            #pragma unroll
            for (int mi = 0; mi < 4; mi++) LDSM_X4(a[mi], aw + mi * 2048 + aq);
            uint32_t b[4][4];
            #pragma unroll
            for (int nj = 0; nj < 4; nj++) LDSM_X4(b[nj], bw + nj * 2048 + bq);
            #pragma unroll
            for (int mi = 0; mi < 4; mi++)
                #pragma unroll
                for (int ni = 0; ni < 8; ni++)
                    MMA16816(c[mi][ni], a[mi], b[ni >> 1][(ni & 1) * 2], b[ni >> 1][(ni & 1) * 2 + 1]);
        }

        CP_WAIT1();
        __syncthreads();
    }

    // ---- fused epilogue ----
    const int gid = lane >> 2, tig = lane & 3;
    const float scale = -2.0e-3f;  // 1/(-500)

    #pragma unroll
    for (int mi = 0; mi < 4; mi++) {
        const int r0 = wm * 64 + mi * 16 + gid;
        const float xs0 = s_xsq[r0];
        const float xs1 = s_xsq[r0 + 8];
        float* o0 = out + (size_t)(bm + r0) * S_ROWS + bn;
        float* o1 = o0 + (size_t)8 * S_ROWS;
        #pragma unroll
        for (int ni = 0; ni < 8; ni++) {
            const int col = wn * 64 + ni * 8 + tig * 2;
            const float ms0 = s_msq[col];
            const float ms1 = s_msq[col + 1];
            float2 v0, v1;
            v0.x = (xs0 + ms0 - 2.f * c[mi][ni][0]) * scale;
            v0.y = (xs0 + ms1 - 2.f * c[mi][ni][1]) * scale;
            v1.x = (xs1 + ms0 - 2.f * c[mi][ni][2]) * scale;
            v1.y = (xs1 + ms1 - 2.f * c[mi][ni][3]) * scale;
            *reinterpret_cast<float2*>(o0 + col) = v0;
            *reinterpret_cast<float2*>(o1 + col) = v1;
        }
    }
}

// ---------------------------------------------------------------------------
extern "C" void kernel_launch(void* const* d_in, const int* in_sizes, int n_in,
                              void* d_out, int out_size) {
    const float* observation        = (const float*)d_in[0];  // [4096, 2496]
    const float* observation_matrix = (const float*)d_in[1];  // [2048, 2496]
    float* out = (float*)d_out;                                // [4096, 2048]

    const int conv_blocks = (B_ROWS + S_ROWS) / CONV_WPB;  // 768
    convert_fused<<<conv_blocks, 256>>>(observation, observation_matrix);

    const int dyn_bytes = NSTAGE * STAGE_BYTES + 1024;  // 99328
    cudaFuncSetAttribute(gemm_sqdist_mma, cudaFuncAttributeMaxDynamicSharedMemorySize, dyn_bytes);
    dim3 grid(S_ROWS / BN, B_ROWS / BM);  // (16, 32) = 512 CTAs
    gemm_sqdist_mma<<<grid, 128, dyn_bytes>>>(out);
}